// round 8
// baseline (speedup 1.0000x reference)
#include <cuda_runtime.h>
#include <cuda_fp16.h>
#include <math.h>

#define BB   8
#define NPTS 8192
#define SS   2048
#define SHALF (SS / 2)
#define CC   256
#define KNN  8

// Scratch (no allocation allowed)
__device__ __half g_featH[BB * SS * CC];          // [B][S][C] fp16, 8.4 MB
__device__ int    g_idx[BB * NPTS * KNN];         // 2 MB (final)
__device__ float  g_w  [BB * NPTS * KNN];         // 2 MB (final)
__device__ float  g_pd[BB * NPTS * 2 * KNN];      // partial dists, 4.2 MB
__device__ int    g_pi[BB * NPTS * 2 * KNN];      // partial idxs,  4.2 MB

// ---------------------------------------------------------------------------
// Kernel 0: transpose + fp16-convert sparse_feat [B,C,S] -> g_featH [B,S,C]
// ---------------------------------------------------------------------------
__global__ void transpose_feat_kernel(const float* __restrict__ feat) {
    __shared__ float tile[32][33];
    int b  = blockIdx.z;
    int s0 = blockIdx.x * 32;
    int c0 = blockIdx.y * 32;
    const float* src = feat + (size_t)b * CC * SS;

    #pragma unroll
    for (int i = threadIdx.y; i < 32; i += 8) {
        tile[i][threadIdx.x] = src[(size_t)(c0 + i) * SS + s0 + threadIdx.x];
    }
    __syncthreads();
    __half* dst = g_featH + (size_t)b * SS * CC;
    #pragma unroll
    for (int i = threadIdx.y; i < 32; i += 8) {
        dst[(size_t)(s0 + i) * CC + c0 + threadIdx.x] =
            __float2half(tile[threadIdx.x][i]);
    }
}

// ---------------------------------------------------------------------------
// Kernel 1: split-S KNN. Each block scans ONE HALF (1024 pts) of the sparse
// set for 128 queries -> 1024 blocks (2x occupancy vs full-scan: 16KB smem).
// Direct (p-q)^2 metric (REQUIRED — R2). Group-of-4 warp-vote gate; inside a
// taken group the 4 insert bodies run if-converted WITHOUT inner votes
// (inner votes pass ~99% when group taken -> pure overhead).
// ---------------------------------------------------------------------------
#define INSERT_NOVOTE(d, sidx)                                               \
    {                                                                        \
        bool c0 = (d) < dist[0];                                             \
        bool c1 = (d) < dist[1];                                             \
        bool c2 = (d) < dist[2];                                             \
        bool c3 = (d) < dist[3];                                             \
        bool c4 = (d) < dist[4];                                             \
        bool c5 = (d) < dist[5];                                             \
        bool c6 = (d) < dist[6];                                             \
        bool c7 = (d) < dist[7];                                             \
        float n0 = c1 ? dist[1] : (c0 ? (d) : dist[0]);                      \
        int   m0 = c1 ? nidx[1] : (c0 ? (sidx) : nidx[0]);                   \
        float n1 = c2 ? dist[2] : (c1 ? (d) : dist[1]);                      \
        int   m1 = c2 ? nidx[2] : (c1 ? (sidx) : nidx[1]);                   \
        float n2 = c3 ? dist[3] : (c2 ? (d) : dist[2]);                      \
        int   m2 = c3 ? nidx[3] : (c2 ? (sidx) : nidx[2]);                   \
        float n3 = c4 ? dist[4] : (c3 ? (d) : dist[3]);                      \
        int   m3 = c4 ? nidx[4] : (c3 ? (sidx) : nidx[3]);                   \
        float n4 = c5 ? dist[5] : (c4 ? (d) : dist[4]);                      \
        int   m4 = c5 ? nidx[5] : (c4 ? (sidx) : nidx[4]);                   \
        float n5 = c6 ? dist[6] : (c5 ? (d) : dist[5]);                      \
        int   m5 = c6 ? nidx[6] : (c5 ? (sidx) : nidx[5]);                   \
        float n6 = c7 ? dist[7] : (c6 ? (d) : dist[6]);                      \
        int   m6 = c7 ? nidx[7] : (c6 ? (sidx) : nidx[6]);                   \
        float n7 = c7 ? (d) : dist[7];                                       \
        int   m7 = c7 ? (sidx) : nidx[7];                                    \
        dist[0] = n0; nidx[0] = m0;                                          \
        dist[1] = n1; nidx[1] = m1;                                          \
        dist[2] = n2; nidx[2] = m2;                                          \
        dist[3] = n3; nidx[3] = m3;                                          \
        dist[4] = n4; nidx[4] = m4;                                          \
        dist[5] = n5; nidx[5] = m5;                                          \
        dist[6] = n6; nidx[6] = m6;                                          \
        dist[7] = n7; nidx[7] = m7;                                          \
    }

__global__ void __launch_bounds__(128)
knn_part_kernel(const float* __restrict__ xyz,
                const float* __restrict__ sxyz) {
    __shared__ float4 sp[SHALF];   // 16 KB
    int b    = blockIdx.y;
    int half = blockIdx.x & 1;
    int tile = blockIdx.x >> 1;
    int s0g  = half * SHALF;

    const float* sb = sxyz + (size_t)b * 3 * SS;
    for (int s = threadIdx.x; s < SHALF; s += 128) {
        int sg = s0g + s;
        sp[s] = make_float4(sb[sg], sb[SS + sg], sb[2 * SS + sg], 0.0f);
    }
    __syncthreads();

    int n = tile * 128 + threadIdx.x;
    const float* xb = xyz + (size_t)b * 3 * NPTS;
    float qx = xb[n];
    float qy = xb[NPTS + n];
    float qz = xb[2 * NPTS + n];

    float dist[KNN];     // descending: dist[0] = current max
    int   nidx[KNN];
    #pragma unroll
    for (int k = 0; k < KNN; k++) { dist[k] = 3.4e38f; nidx[k] = 0; }

    for (int s = 0; s < SHALF; s += 4) {
        float4 p0 = sp[s + 0];
        float4 p1 = sp[s + 1];
        float4 p2 = sp[s + 2];
        float4 p3 = sp[s + 3];
        float dx0 = qx - p0.x, dy0 = qy - p0.y, dz0 = qz - p0.z;
        float dx1 = qx - p1.x, dy1 = qy - p1.y, dz1 = qz - p1.z;
        float dx2 = qx - p2.x, dy2 = qy - p2.y, dz2 = qz - p2.z;
        float dx3 = qx - p3.x, dy3 = qy - p3.y, dz3 = qz - p3.z;
        float d0 = fmaf(dx0, dx0, fmaf(dy0, dy0, dz0 * dz0));
        float d1 = fmaf(dx1, dx1, fmaf(dy1, dy1, dz1 * dz1));
        float d2 = fmaf(dx2, dx2, fmaf(dy2, dy2, dz2 * dz2));
        float d3 = fmaf(dx3, dx3, fmaf(dy3, dy3, dz3 * dz3));
        float m = fminf(fminf(d0, d1), fminf(d2, d3));
        if (__any_sync(0xffffffffu, m < dist[0])) {
            INSERT_NOVOTE(d0, s + 0)
            INSERT_NOVOTE(d1, s + 1)
            INSERT_NOVOTE(d2, s + 2)
            INSERT_NOVOTE(d3, s + 3)
        }
    }

    // store partial top-8 ASCENDING with global s indices
    int base = ((b * NPTS + n) * 2 + half) * KNN;
    #pragma unroll
    for (int k = 0; k < KNN; k++) {
        g_pd[base + k] = dist[KNN - 1 - k];
        g_pi[base + k] = nidx[KNN - 1 - k] + s0g;
    }
}

// ---------------------------------------------------------------------------
// Kernel 1b: merge two ascending top-8 lists via half-cleaner, then weights.
// min(a[i], b[7-i]) yields exactly the 8 smallest of the 16 (bitonic
// half-cleaner property). Weight formula is permutation-invariant -> no sort.
// Tie (==) prefers first half (lower s index), matching insertion semantics.
// ---------------------------------------------------------------------------
__global__ void __launch_bounds__(256)
merge_kernel() {
    int g = blockIdx.x * 256 + threadIdx.x;    // 0 .. BB*NPTS-1
    int base = g * 2 * KNN;

    float ad[KNN], bd[KNN];
    int   ai[KNN], bi[KNN];
    #pragma unroll
    for (int k = 0; k < KNN; k++) {
        ad[k] = g_pd[base + k];
        ai[k] = g_pi[base + k];
        bd[k] = g_pd[base + KNN + k];
        bi[k] = g_pi[base + KNN + k];
    }

    float d[KNN];
    int   ix[KNN];
    #pragma unroll
    for (int k = 0; k < KNN; k++) {
        bool ta = ad[k] <= bd[KNN - 1 - k];
        d[k]  = ta ? ad[k] : bd[KNN - 1 - k];
        ix[k] = ta ? ai[k] : bi[KNN - 1 - k];
    }

    float inv[KNN];
    float ws = 0.0f;
    #pragma unroll
    for (int k = 0; k < KNN; k++) {
        float dd = sqrtf(d[k]);
        dd = fmaxf(dd, 1e-10f);
        inv[k] = 1.0f / dd;
        ws += inv[k];
    }
    float rws = 1.0f / ws;

    int obase = g * KNN;
    #pragma unroll
    for (int k = 0; k < KNN; k++) {
        g_idx[obase + k] = ix[k];
        g_w[obase + k]   = inv[k] * rws;
    }
}

// ---------------------------------------------------------------------------
// Kernel 2: weighted feature interpolation, fp16 gathers, fp32 accumulate.
// ---------------------------------------------------------------------------
__global__ void interp_kernel(float* __restrict__ out) {
    __shared__ float tile[32][CC + 1];   // 32 x 257 floats
    __shared__ int   s_idx[32][KNN];
    __shared__ float s_w[32][KNN];

    int b  = blockIdx.y;
    int n0 = blockIdx.x * 32;
    int tid = threadIdx.x;

    if (tid < 32 * KNN) {
        int nn = tid / KNN;
        int kk = tid % KNN;
        int base = (b * NPTS + n0 + nn) * KNN;
        s_idx[nn][kk] = g_idx[base + kk];
        s_w[nn][kk]   = g_w[base + kk];
    }
    __syncthreads();

    int tc    = tid & 63;
    int qbase = tid >> 6;
    const __half* fb = g_featH + (size_t)b * SS * CC + tc * 4;

    #pragma unroll
    for (int q = qbase; q < 32; q += 16) {
        float a0 = 0.f, a1 = 0.f, a2 = 0.f, a3 = 0.f;
        #pragma unroll
        for (int k = 0; k < KNN; k++) {
            int   si = s_idx[q][k];
            float wt = s_w[q][k];
            uint2 raw = *(const uint2*)(fb + (size_t)si * CC);
            __half2 h0 = *reinterpret_cast<__half2*>(&raw.x);
            __half2 h1 = *reinterpret_cast<__half2*>(&raw.y);
            float2 f0 = __half22float2(h0);
            float2 f1 = __half22float2(h1);
            a0 = fmaf(wt, f0.x, a0);
            a1 = fmaf(wt, f0.y, a1);
            a2 = fmaf(wt, f1.x, a2);
            a3 = fmaf(wt, f1.y, a3);
        }
        int c = tc * 4;
        tile[q][c + 0] = a0;
        tile[q][c + 1] = a1;
        tile[q][c + 2] = a2;
        tile[q][c + 3] = a3;
    }
    __syncthreads();

    int lane = tid & 31;
    int w    = tid >> 5;
    float* ob = out + (size_t)b * CC * NPTS + n0 + lane;
    #pragma unroll
    for (int j = 0; j < 8; j++) {
        int c = w + j * 32;
        ob[(size_t)c * NPTS] = tile[lane][c];
    }
}

// ---------------------------------------------------------------------------
extern "C" void kernel_launch(void* const* d_in, const int* in_sizes, int n_in,
                              void* d_out, int out_size) {
    const float* xyz         = (const float*)d_in[0];  // [B,3,N]
    const float* sparse_xyz  = (const float*)d_in[1];  // [B,3,S]
    const float* sparse_feat = (const float*)d_in[2];  // [B,C,S]
    float* out = (float*)d_out;                        // [B,C,N]

    transpose_feat_kernel<<<dim3(SS / 32, CC / 32, BB), dim3(32, 8)>>>(sparse_feat);
    knn_part_kernel<<<dim3((NPTS / 128) * 2, BB), 128>>>(xyz, sparse_xyz);
    merge_kernel<<<(BB * NPTS) / 256, 256>>>();
    interp_kernel<<<dim3(NPTS / 32, BB), 1024>>>(out);
}

// round 9
// speedup vs baseline: 1.1987x; 1.1987x over previous
#include <cuda_runtime.h>
#include <cuda_fp16.h>
#include <math.h>

#define BB   8
#define NPTS 8192
#define SS   2048
#define CC   256
#define KNN  8

#define GRID 8
#define NCELL (GRID * GRID * GRID)
#define GLO  (-4.5f)
#define GH   (9.0f / GRID)          // 1.125

// Scratch (no allocation allowed)
__device__ __half g_featH[BB * SS * CC];       // [B][S][C] fp16, 8.4 MB
__device__ int    g_idx[BB * NPTS * KNN];      // 2 MB
__device__ float  g_w  [BB * NPTS * KNN];      // 2 MB
__device__ float4 g_binned[BB * SS];           // binned points (x,y,z,idx-bits)
__device__ int    g_cellstart[BB][NCELL + 1];  // CSR cell offsets

// ---------------------------------------------------------------------------
// Kernel 0: transpose + fp16-convert sparse_feat [B,C,S] -> g_featH [B,S,C]
// ---------------------------------------------------------------------------
__global__ void transpose_feat_kernel(const float* __restrict__ feat) {
    __shared__ float tile[32][33];
    int b  = blockIdx.z;
    int s0 = blockIdx.x * 32;
    int c0 = blockIdx.y * 32;
    const float* src = feat + (size_t)b * CC * SS;

    #pragma unroll
    for (int i = threadIdx.y; i < 32; i += 8) {
        tile[i][threadIdx.x] = src[(size_t)(c0 + i) * SS + s0 + threadIdx.x];
    }
    __syncthreads();
    __half* dst = g_featH + (size_t)b * SS * CC;
    #pragma unroll
    for (int i = threadIdx.y; i < 32; i += 8) {
        dst[(size_t)(s0 + i) * CC + c0 + threadIdx.x] =
            __float2half(tile[threadIdx.x][i]);
    }
}

// ---------------------------------------------------------------------------
// Kernel A: bin sparse points into an 8^3 grid (counting sort), one block
// per batch. Coordinates clamp into edge cells (safe: clamped outliers are
// farther than their cell's nominal box, so box-distance pruning stays valid).
// ---------------------------------------------------------------------------
__device__ __forceinline__ int cell_of(float x, float y, float z) {
    int cx = (int)floorf((x - GLO) / GH);
    int cy = (int)floorf((y - GLO) / GH);
    int cz = (int)floorf((z - GLO) / GH);
    cx = min(max(cx, 0), GRID - 1);
    cy = min(max(cy, 0), GRID - 1);
    cz = min(max(cz, 0), GRID - 1);
    return (cx * GRID + cy) * GRID + cz;
}

__global__ void __launch_bounds__(512)
bin_kernel(const float* __restrict__ sxyz) {
    __shared__ int hist[NCELL];
    __shared__ int curs[NCELL];
    int b   = blockIdx.x;
    int tid = threadIdx.x;

    for (int c = tid; c < NCELL; c += 512) hist[c] = 0;
    __syncthreads();

    const float* sb = sxyz + (size_t)b * 3 * SS;
    float px[4], py[4], pz[4];
    int   pc[4];
    #pragma unroll
    for (int j = 0; j < 4; j++) {
        int s = tid * 4 + j;
        px[j] = sb[s];
        py[j] = sb[SS + s];
        pz[j] = sb[2 * SS + s];
        pc[j] = cell_of(px[j], py[j], pz[j]);
        atomicAdd(&hist[pc[j]], 1);
    }
    __syncthreads();

    if (tid == 0) {                       // serial exclusive scan (tiny)
        int run = 0;
        for (int c = 0; c < NCELL; c++) {
            int h = hist[c];
            curs[c] = run;
            g_cellstart[b][c] = run;
            run += h;
        }
        g_cellstart[b][NCELL] = run;      // == SS
    }
    __syncthreads();

    #pragma unroll
    for (int j = 0; j < 4; j++) {
        int s = tid * 4 + j;
        int pos = atomicAdd(&curs[pc[j]], 1);
        g_binned[(size_t)b * SS + pos] =
            make_float4(px[j], py[j], pz[j], __int_as_float(s));
    }
}

// ---------------------------------------------------------------------------
// Kernel 1: grid-accelerated exact KNN (K=8) + inverse-distance weights.
// Ring expansion by Chebyshev radius r; exact stop: after ring r the scanned
// spatial box B_r contains every unscanned candidate's lower-bound region,
// so stop when dist8 <= margin(q, B_r)^2. Worst case scans all cells once.
// Direct (p-q)^2 metric (REQUIRED — R2 lesson).
// ---------------------------------------------------------------------------
#define INSERT_NOVOTE(d, sidx)                                               \
    {                                                                        \
        bool c0 = (d) < dist[0];                                             \
        bool c1 = (d) < dist[1];                                             \
        bool c2 = (d) < dist[2];                                             \
        bool c3 = (d) < dist[3];                                             \
        bool c4 = (d) < dist[4];                                             \
        bool c5 = (d) < dist[5];                                             \
        bool c6 = (d) < dist[6];                                             \
        bool c7 = (d) < dist[7];                                             \
        float n0 = c1 ? dist[1] : (c0 ? (d) : dist[0]);                      \
        int   m0 = c1 ? nidx[1] : (c0 ? (sidx) : nidx[0]);                   \
        float n1 = c2 ? dist[2] : (c1 ? (d) : dist[1]);                      \
        int   m1 = c2 ? nidx[2] : (c1 ? (sidx) : nidx[1]);                   \
        float n2 = c3 ? dist[3] : (c2 ? (d) : dist[2]);                      \
        int   m2 = c3 ? nidx[3] : (c2 ? (sidx) : nidx[2]);                   \
        float n3 = c4 ? dist[4] : (c3 ? (d) : dist[3]);                      \
        int   m3 = c4 ? nidx[4] : (c3 ? (sidx) : nidx[3]);                   \
        float n4 = c5 ? dist[5] : (c4 ? (d) : dist[4]);                      \
        int   m4 = c5 ? nidx[5] : (c4 ? (sidx) : nidx[4]);                   \
        float n5 = c6 ? dist[6] : (c5 ? (d) : dist[5]);                      \
        int   m5 = c6 ? nidx[6] : (c5 ? (sidx) : nidx[5]);                   \
        float n6 = c7 ? dist[7] : (c6 ? (d) : dist[6]);                      \
        int   m6 = c7 ? nidx[7] : (c6 ? (sidx) : nidx[6]);                   \
        float n7 = c7 ? (d) : dist[7];                                       \
        int   m7 = c7 ? (sidx) : nidx[7];                                    \
        dist[0] = n0; nidx[0] = m0;                                          \
        dist[1] = n1; nidx[1] = m1;                                          \
        dist[2] = n2; nidx[2] = m2;                                          \
        dist[3] = n3; nidx[3] = m3;                                          \
        dist[4] = n4; nidx[4] = m4;                                          \
        dist[5] = n5; nidx[5] = m5;                                          \
        dist[6] = n6; nidx[6] = m6;                                          \
        dist[7] = n7; nidx[7] = m7;                                          \
    }

__global__ void __launch_bounds__(128)
knn_grid_kernel(const float* __restrict__ xyz) {
    __shared__ float4 sp[SS];          // binned points, 32 KB
    __shared__ int    cs[NCELL + 1];   // cell starts
    int b = blockIdx.y;

    {
        const float4* gb = g_binned + (size_t)b * SS;
        for (int s = threadIdx.x; s < SS; s += 128) sp[s] = gb[s];
        for (int c = threadIdx.x; c <= NCELL; c += 128) cs[c] = g_cellstart[b][c];
    }
    __syncthreads();

    int n = blockIdx.x * 128 + threadIdx.x;
    const float* xb = xyz + (size_t)b * 3 * NPTS;
    float qx = xb[n];
    float qy = xb[NPTS + n];
    float qz = xb[2 * NPTS + n];

    int hx = min(max((int)floorf((qx - GLO) / GH), 0), GRID - 1);
    int hy = min(max((int)floorf((qy - GLO) / GH), 0), GRID - 1);
    int hz = min(max((int)floorf((qz - GLO) / GH), 0), GRID - 1);

    float dist[KNN];     // descending: dist[0] = current max (8th best)
    int   nidx[KNN];
    #pragma unroll
    for (int k = 0; k < KNN; k++) { dist[k] = 3.4e38f; nidx[k] = 0; }

    for (int r = 0; r < GRID; r++) {
        int lx = max(hx - r, 0), ux = min(hx + r, GRID - 1);
        int ly = max(hy - r, 0), uy = min(hy + r, GRID - 1);
        int lz = max(hz - r, 0), uz = min(hz + r, GRID - 1);

        for (int zx = lx; zx <= ux; zx++) {
            int ax = ::abs(zx - hx);
            for (int zy = ly; zy <= uy; zy++) {
                int axy = max(ax, ::abs(zy - hy));
                for (int zz = lz; zz <= uz; zz++) {
                    int cheb = max(axy, ::abs(zz - hz));
                    if (cheb != r) continue;     // only the new shell
                    int cid = (zx * GRID + zy) * GRID + zz;
                    int j0 = cs[cid], j1 = cs[cid + 1];
                    for (int j = j0; j < j1; j++) {
                        float4 p = sp[j];
                        float dx = qx - p.x;
                        float dy = qy - p.y;
                        float dz = qz - p.z;
                        float d = fmaf(dx, dx, fmaf(dy, dy, dz * dz));
                        if (d < dist[0]) {
                            int sidx = __float_as_int(p.w);
                            INSERT_NOVOTE(d, sidx)
                        }
                    }
                }
            }
        }

        // Exact termination: margin = min distance from q to any non-edge
        // face of the scanned spatial box (edge faces have nothing beyond).
        float m = 3.4e38f;
        if (lx > 0)        m = fminf(m, qx - (lx * GH + GLO));
        if (ux < GRID - 1) m = fminf(m, ((ux + 1) * GH + GLO) - qx);
        if (ly > 0)        m = fminf(m, qy - (ly * GH + GLO));
        if (uy < GRID - 1) m = fminf(m, ((uy + 1) * GH + GLO) - qy);
        if (lz > 0)        m = fminf(m, qz - (lz * GH + GLO));
        if (uz < GRID - 1) m = fminf(m, ((uz + 1) * GH + GLO) - qz);
        if (m >= 3.4e38f) break;                 // whole grid scanned
        if (m > 0.0f && dist[0] <= m * m) break; // provably done
    }

    // inverse-distance weights (reference formula; permutation-invariant)
    float inv[KNN];
    float ws = 0.0f;
    #pragma unroll
    for (int k = 0; k < KNN; k++) {
        float dd = sqrtf(dist[k]);
        dd = fmaxf(dd, 1e-10f);
        inv[k] = 1.0f / dd;
        ws += inv[k];
    }
    float rws = 1.0f / ws;

    int base = (b * NPTS + n) * KNN;
    #pragma unroll
    for (int k = 0; k < KNN; k++) {
        g_idx[base + k] = nidx[k];
        g_w[base + k]   = inv[k] * rws;
    }
}

// ---------------------------------------------------------------------------
// Kernel 2: weighted feature interpolation, fp16 gathers, fp32 accumulate.
// ---------------------------------------------------------------------------
__global__ void interp_kernel(float* __restrict__ out) {
    __shared__ float tile[32][CC + 1];   // 32 x 257 floats
    __shared__ int   s_idx[32][KNN];
    __shared__ float s_w[32][KNN];

    int b  = blockIdx.y;
    int n0 = blockIdx.x * 32;
    int tid = threadIdx.x;

    if (tid < 32 * KNN) {
        int nn = tid / KNN;
        int kk = tid % KNN;
        int base = (b * NPTS + n0 + nn) * KNN;
        s_idx[nn][kk] = g_idx[base + kk];
        s_w[nn][kk]   = g_w[base + kk];
    }
    __syncthreads();

    int tc    = tid & 63;
    int qbase = tid >> 6;
    const __half* fb = g_featH + (size_t)b * SS * CC + tc * 4;

    #pragma unroll
    for (int q = qbase; q < 32; q += 16) {
        float a0 = 0.f, a1 = 0.f, a2 = 0.f, a3 = 0.f;
        #pragma unroll
        for (int k = 0; k < KNN; k++) {
            int   si = s_idx[q][k];
            float wt = s_w[q][k];
            uint2 raw = *(const uint2*)(fb + (size_t)si * CC);
            __half2 h0 = *reinterpret_cast<__half2*>(&raw.x);
            __half2 h1 = *reinterpret_cast<__half2*>(&raw.y);
            float2 f0 = __half22float2(h0);
            float2 f1 = __half22float2(h1);
            a0 = fmaf(wt, f0.x, a0);
            a1 = fmaf(wt, f0.y, a1);
            a2 = fmaf(wt, f1.x, a2);
            a3 = fmaf(wt, f1.y, a3);
        }
        int c = tc * 4;
        tile[q][c + 0] = a0;
        tile[q][c + 1] = a1;
        tile[q][c + 2] = a2;
        tile[q][c + 3] = a3;
    }
    __syncthreads();

    int lane = tid & 31;
    int w    = tid >> 5;
    float* ob = out + (size_t)b * CC * NPTS + n0 + lane;
    #pragma unroll
    for (int j = 0; j < 8; j++) {
        int c = w + j * 32;
        ob[(size_t)c * NPTS] = tile[lane][c];
    }
}

// ---------------------------------------------------------------------------
extern "C" void kernel_launch(void* const* d_in, const int* in_sizes, int n_in,
                              void* d_out, int out_size) {
    const float* xyz         = (const float*)d_in[0];  // [B,3,N]
    const float* sparse_xyz  = (const float*)d_in[1];  // [B,3,S]
    const float* sparse_feat = (const float*)d_in[2];  // [B,C,S]
    float* out = (float*)d_out;                        // [B,C,N]

    transpose_feat_kernel<<<dim3(SS / 32, CC / 32, BB), dim3(32, 8)>>>(sparse_feat);
    bin_kernel<<<BB, 512>>>(sparse_xyz);
    knn_grid_kernel<<<dim3(NPTS / 128, BB), 128>>>(xyz);
    interp_kernel<<<dim3(NPTS / 32, BB), 1024>>>(out);
}

// round 10
// speedup vs baseline: 1.4980x; 1.2497x over previous
#include <cuda_runtime.h>
#include <cuda_fp16.h>
#include <math.h>

#define BB   8
#define NPTS 8192
#define SS   2048
#define CC   256
#define KNN  8

#define GRID 8
#define NCELL (GRID * GRID * GRID)
#define GLO  (-4.5f)
#define GH   (9.0f / GRID)          // 1.125

// Scratch (no allocation allowed)
__device__ __half g_featH[BB * SS * CC];       // [B][S][C] fp16, 8.4 MB
__device__ int    g_idx[BB * NPTS * KNN];      // 2 MB
__device__ float  g_w  [BB * NPTS * KNN];      // 2 MB
__device__ float4 g_binned[BB * SS];           // binned points (x,y,z,idx-bits)
__device__ int    g_cellstart[BB][NCELL + 1];  // CSR cell offsets
__device__ int    g_qorder[BB * NPTS];         // queries sorted by home cell

// ---------------------------------------------------------------------------
// Kernel 0: transpose + fp16-convert sparse_feat [B,C,S] -> g_featH [B,S,C]
// ---------------------------------------------------------------------------
__global__ void transpose_feat_kernel(const float* __restrict__ feat) {
    __shared__ float tile[32][33];
    int b  = blockIdx.z;
    int s0 = blockIdx.x * 32;
    int c0 = blockIdx.y * 32;
    const float* src = feat + (size_t)b * CC * SS;

    #pragma unroll
    for (int i = threadIdx.y; i < 32; i += 8) {
        tile[i][threadIdx.x] = src[(size_t)(c0 + i) * SS + s0 + threadIdx.x];
    }
    __syncthreads();
    __half* dst = g_featH + (size_t)b * SS * CC;
    #pragma unroll
    for (int i = threadIdx.y; i < 32; i += 8) {
        dst[(size_t)(s0 + i) * CC + c0 + threadIdx.x] =
            __float2half(tile[threadIdx.x][i]);
    }
}

// ---------------------------------------------------------------------------
// Grid helpers. Coordinates clamp into edge cells (safe for the pruning
// bound: clamped outliers are farther than their cell's nominal box).
// ---------------------------------------------------------------------------
__device__ __forceinline__ int cell_of(float x, float y, float z) {
    int cx = (int)floorf((x - GLO) / GH);
    int cy = (int)floorf((y - GLO) / GH);
    int cz = (int)floorf((z - GLO) / GH);
    cx = min(max(cx, 0), GRID - 1);
    cy = min(max(cy, 0), GRID - 1);
    cz = min(max(cz, 0), GRID - 1);
    return (cx * GRID + cy) * GRID + cz;
}

// ---------------------------------------------------------------------------
// Kernel A: bin sparse points into the 8^3 grid (counting sort), 1 blk/batch.
// ---------------------------------------------------------------------------
__global__ void __launch_bounds__(512)
bin_kernel(const float* __restrict__ sxyz) {
    __shared__ int hist[NCELL];
    __shared__ int curs[NCELL];
    int b   = blockIdx.x;
    int tid = threadIdx.x;

    for (int c = tid; c < NCELL; c += 512) hist[c] = 0;
    __syncthreads();

    const float* sb = sxyz + (size_t)b * 3 * SS;
    float px[4], py[4], pz[4];
    int   pc[4];
    #pragma unroll
    for (int j = 0; j < 4; j++) {
        int s = tid * 4 + j;
        px[j] = sb[s];
        py[j] = sb[SS + s];
        pz[j] = sb[2 * SS + s];
        pc[j] = cell_of(px[j], py[j], pz[j]);
        atomicAdd(&hist[pc[j]], 1);
    }
    __syncthreads();

    if (tid == 0) {
        int run = 0;
        for (int c = 0; c < NCELL; c++) {
            int h = hist[c];
            curs[c] = run;
            g_cellstart[b][c] = run;
            run += h;
        }
        g_cellstart[b][NCELL] = run;
    }
    __syncthreads();

    #pragma unroll
    for (int j = 0; j < 4; j++) {
        int s = tid * 4 + j;
        int pos = atomicAdd(&curs[pc[j]], 1);
        g_binned[(size_t)b * SS + pos] =
            make_float4(px[j], py[j], pz[j], __int_as_float(s));
    }
}

// ---------------------------------------------------------------------------
// Kernel B: counting-sort QUERIES by home cell, 1 block (1024 thr) / batch.
// Makes warp lanes in the knn kernel spatially coherent (same home cell),
// so ring traversal and candidate scans overlap instead of unioning.
// ---------------------------------------------------------------------------
__global__ void __launch_bounds__(1024)
qsort_kernel(const float* __restrict__ xyz) {
    __shared__ int hist[NCELL];
    __shared__ int curs[NCELL];
    int b   = blockIdx.x;
    int tid = threadIdx.x;

    for (int c = tid; c < NCELL; c += 1024) hist[c] = 0;
    __syncthreads();

    const float* xb = xyz + (size_t)b * 3 * NPTS;
    int qc[8];
    #pragma unroll
    for (int j = 0; j < 8; j++) {
        int n = tid * 8 + j;
        qc[j] = cell_of(xb[n], xb[NPTS + n], xb[2 * NPTS + n]);
        atomicAdd(&hist[qc[j]], 1);
    }
    __syncthreads();

    if (tid == 0) {
        int run = 0;
        for (int c = 0; c < NCELL; c++) {
            curs[c] = run;
            run += hist[c];
        }
    }
    __syncthreads();

    #pragma unroll
    for (int j = 0; j < 8; j++) {
        int n = tid * 8 + j;
        int pos = atomicAdd(&curs[qc[j]], 1);
        g_qorder[b * NPTS + pos] = n;
    }
}

// ---------------------------------------------------------------------------
// Kernel 1: grid-accelerated exact KNN, spatially-coherent warps.
// Traversal + termination identical to R9 (proven exact); only the query
// visit order differs (lane -> sorted query). Results scatter to original
// slots. Direct (p-q)^2 metric (REQUIRED — R2 lesson).
// ---------------------------------------------------------------------------
#define INSERT_NOVOTE(d, sidx)                                               \
    {                                                                        \
        bool c0 = (d) < dist[0];                                             \
        bool c1 = (d) < dist[1];                                             \
        bool c2 = (d) < dist[2];                                             \
        bool c3 = (d) < dist[3];                                             \
        bool c4 = (d) < dist[4];                                             \
        bool c5 = (d) < dist[5];                                             \
        bool c6 = (d) < dist[6];                                             \
        bool c7 = (d) < dist[7];                                             \
        float n0 = c1 ? dist[1] : (c0 ? (d) : dist[0]);                      \
        int   m0 = c1 ? nidx[1] : (c0 ? (sidx) : nidx[0]);                   \
        float n1 = c2 ? dist[2] : (c1 ? (d) : dist[1]);                      \
        int   m1 = c2 ? nidx[2] : (c1 ? (sidx) : nidx[1]);                   \
        float n2 = c3 ? dist[3] : (c2 ? (d) : dist[2]);                      \
        int   m2 = c3 ? nidx[3] : (c2 ? (sidx) : nidx[2]);                   \
        float n3 = c4 ? dist[4] : (c3 ? (d) : dist[3]);                      \
        int   m3 = c4 ? nidx[4] : (c3 ? (sidx) : nidx[3]);                   \
        float n4 = c5 ? dist[5] : (c4 ? (d) : dist[4]);                      \
        int   m4 = c5 ? nidx[5] : (c4 ? (sidx) : nidx[4]);                   \
        float n5 = c6 ? dist[6] : (c5 ? (d) : dist[5]);                      \
        int   m5 = c6 ? nidx[6] : (c5 ? (sidx) : nidx[5]);                   \
        float n6 = c7 ? dist[7] : (c6 ? (d) : dist[6]);                      \
        int   m6 = c7 ? nidx[7] : (c6 ? (sidx) : nidx[6]);                   \
        float n7 = c7 ? (d) : dist[7];                                       \
        int   m7 = c7 ? (sidx) : nidx[7];                                    \
        dist[0] = n0; nidx[0] = m0;                                          \
        dist[1] = n1; nidx[1] = m1;                                          \
        dist[2] = n2; nidx[2] = m2;                                          \
        dist[3] = n3; nidx[3] = m3;                                          \
        dist[4] = n4; nidx[4] = m4;                                          \
        dist[5] = n5; nidx[5] = m5;                                          \
        dist[6] = n6; nidx[6] = m6;                                          \
        dist[7] = n7; nidx[7] = m7;                                          \
    }

__global__ void __launch_bounds__(128)
knn_grid_kernel(const float* __restrict__ xyz) {
    __shared__ float4 sp[SS];          // binned points, 32 KB
    __shared__ int    cs[NCELL + 1];   // cell starts
    int b = blockIdx.y;

    {
        const float4* gb = g_binned + (size_t)b * SS;
        for (int s = threadIdx.x; s < SS; s += 128) sp[s] = gb[s];
        for (int c = threadIdx.x; c <= NCELL; c += 128) cs[c] = g_cellstart[b][c];
    }
    __syncthreads();

    int n = g_qorder[b * NPTS + blockIdx.x * 128 + threadIdx.x];
    const float* xb = xyz + (size_t)b * 3 * NPTS;
    float qx = xb[n];
    float qy = xb[NPTS + n];
    float qz = xb[2 * NPTS + n];

    int hx = min(max((int)floorf((qx - GLO) / GH), 0), GRID - 1);
    int hy = min(max((int)floorf((qy - GLO) / GH), 0), GRID - 1);
    int hz = min(max((int)floorf((qz - GLO) / GH), 0), GRID - 1);

    float dist[KNN];     // descending: dist[0] = current max (8th best)
    int   nidx[KNN];
    #pragma unroll
    for (int k = 0; k < KNN; k++) { dist[k] = 3.4e38f; nidx[k] = 0; }

    for (int r = 0; r < GRID; r++) {
        int lx = max(hx - r, 0), ux = min(hx + r, GRID - 1);
        int ly = max(hy - r, 0), uy = min(hy + r, GRID - 1);
        int lz = max(hz - r, 0), uz = min(hz + r, GRID - 1);

        for (int zx = lx; zx <= ux; zx++) {
            int ax = ::abs(zx - hx);
            for (int zy = ly; zy <= uy; zy++) {
                int axy = max(ax, ::abs(zy - hy));
                for (int zz = lz; zz <= uz; zz++) {
                    int cheb = max(axy, ::abs(zz - hz));
                    if (cheb != r) continue;     // only the new shell
                    int cid = (zx * GRID + zy) * GRID + zz;
                    int j0 = cs[cid], j1 = cs[cid + 1];
                    for (int j = j0; j < j1; j++) {
                        float4 p = sp[j];
                        float dx = qx - p.x;
                        float dy = qy - p.y;
                        float dz = qz - p.z;
                        float d = fmaf(dx, dx, fmaf(dy, dy, dz * dz));
                        if (d < dist[0]) {
                            int sidx = __float_as_int(p.w);
                            INSERT_NOVOTE(d, sidx)
                        }
                    }
                }
            }
        }

        // Exact termination: margin = min distance from q to any non-edge
        // face of the scanned spatial box (edge faces have nothing beyond).
        float m = 3.4e38f;
        if (lx > 0)        m = fminf(m, qx - (lx * GH + GLO));
        if (ux < GRID - 1) m = fminf(m, ((ux + 1) * GH + GLO) - qx);
        if (ly > 0)        m = fminf(m, qy - (ly * GH + GLO));
        if (uy < GRID - 1) m = fminf(m, ((uy + 1) * GH + GLO) - qy);
        if (lz > 0)        m = fminf(m, qz - (lz * GH + GLO));
        if (uz < GRID - 1) m = fminf(m, ((uz + 1) * GH + GLO) - qz);
        if (m >= 3.4e38f) break;                 // whole grid scanned
        if (m > 0.0f && dist[0] <= m * m) break; // provably done
    }

    // inverse-distance weights (reference formula; permutation-invariant)
    float inv[KNN];
    float ws = 0.0f;
    #pragma unroll
    for (int k = 0; k < KNN; k++) {
        float dd = sqrtf(dist[k]);
        dd = fmaxf(dd, 1e-10f);
        inv[k] = 1.0f / dd;
        ws += inv[k];
    }
    float rws = 1.0f / ws;

    int base = (b * NPTS + n) * KNN;
    #pragma unroll
    for (int k = 0; k < KNN; k++) {
        g_idx[base + k] = nidx[k];
        g_w[base + k]   = inv[k] * rws;
    }
}

// ---------------------------------------------------------------------------
// Kernel 2: weighted feature interpolation, fp16 gathers, fp32 accumulate.
// ---------------------------------------------------------------------------
__global__ void interp_kernel(float* __restrict__ out) {
    __shared__ float tile[32][CC + 1];   // 32 x 257 floats
    __shared__ int   s_idx[32][KNN];
    __shared__ float s_w[32][KNN];

    int b  = blockIdx.y;
    int n0 = blockIdx.x * 32;
    int tid = threadIdx.x;

    if (tid < 32 * KNN) {
        int nn = tid / KNN;
        int kk = tid % KNN;
        int base = (b * NPTS + n0 + nn) * KNN;
        s_idx[nn][kk] = g_idx[base + kk];
        s_w[nn][kk]   = g_w[base + kk];
    }
    __syncthreads();

    int tc    = tid & 63;
    int qbase = tid >> 6;
    const __half* fb = g_featH + (size_t)b * SS * CC + tc * 4;

    #pragma unroll
    for (int q = qbase; q < 32; q += 16) {
        float a0 = 0.f, a1 = 0.f, a2 = 0.f, a3 = 0.f;
        #pragma unroll
        for (int k = 0; k < KNN; k++) {
            int   si = s_idx[q][k];
            float wt = s_w[q][k];
            uint2 raw = *(const uint2*)(fb + (size_t)si * CC);
            __half2 h0 = *reinterpret_cast<__half2*>(&raw.x);
            __half2 h1 = *reinterpret_cast<__half2*>(&raw.y);
            float2 f0 = __half22float2(h0);
            float2 f1 = __half22float2(h1);
            a0 = fmaf(wt, f0.x, a0);
            a1 = fmaf(wt, f0.y, a1);
            a2 = fmaf(wt, f1.x, a2);
            a3 = fmaf(wt, f1.y, a3);
        }
        int c = tc * 4;
        tile[q][c + 0] = a0;
        tile[q][c + 1] = a1;
        tile[q][c + 2] = a2;
        tile[q][c + 3] = a3;
    }
    __syncthreads();

    int lane = tid & 31;
    int w    = tid >> 5;
    float* ob = out + (size_t)b * CC * NPTS + n0 + lane;
    #pragma unroll
    for (int j = 0; j < 8; j++) {
        int c = w + j * 32;
        ob[(size_t)c * NPTS] = tile[lane][c];
    }
}

// ---------------------------------------------------------------------------
extern "C" void kernel_launch(void* const* d_in, const int* in_sizes, int n_in,
                              void* d_out, int out_size) {
    const float* xyz         = (const float*)d_in[0];  // [B,3,N]
    const float* sparse_xyz  = (const float*)d_in[1];  // [B,3,S]
    const float* sparse_feat = (const float*)d_in[2];  // [B,C,S]
    float* out = (float*)d_out;                        // [B,C,N]

    transpose_feat_kernel<<<dim3(SS / 32, CC / 32, BB), dim3(32, 8)>>>(sparse_feat);
    bin_kernel<<<BB, 512>>>(sparse_xyz);
    qsort_kernel<<<BB, 1024>>>(xyz);
    knn_grid_kernel<<<dim3(NPTS / 128, BB), 128>>>(xyz);
    interp_kernel<<<dim3(NPTS / 32, BB), 1024>>>(out);
}